// round 15
// baseline (speedup 1.0000x reference)
#include <cuda_runtime.h>
#include <cstdint>

// EfficientSHRFFN — FINAL (R12 configuration, best measured).
// Bit-exact semantics (locked R4, rel_err == 0.0 on every passing round):
//   B=262144, NPOS=4, D=64; opcode=3, OP_START=16 -> op_active idx 19
//   NIB_A=0, NIB_B=1, RESULT=2
//   value f32 sum order: strided halving (t0+t2)+(t1+t3), products exact
//   astype(int64) under x64-disabled jax -> int32, float->int32 SATURATES
//   shifts/byte-extract in int32
//
// Convergence evidence (wall / ncu, DRAM%):
//   ITEMS=1 T256        : 84.0  / 81.8  75.8%
//   ITEMS=4 T256        : 82.1  / 74.6  81.5%   (.cs hints: 88.8 wall — rejected)
//   ITEMS=8 T256        : 82.4  / 75.9  80.1%   (occ 49% — rejected)
//   ITEMS=4 T512        : 82.0  / 75.4  80.8%
//   reg-map  T256       : 82.7  / 75.2  81.0%
//   persistent 1216 CTA : 92.3  / 79.4  77.5%   (scattered frontier — rejected)
//   reg-map  T512 i64   : 82.0  / 73.9  82.1%  regs 26  <- WINNER (this file)
//   reg-map  T512 u32   : 81.98 / 74.9  81.2%  regs 32  (tie; worse ncu/regs)
// ~6.5 TB/s is the path-independent LTS/HBM mixed-stream ceiling (B300
// microarch: LTS cap ~6300 B/cyc, LDG == TMA). Kernel is at the roofline;
// residual wall-ncu gap (~7us) is fixed harness/graph-replay cost.

static constexpr long long N_ROWS = 262144;   // B
static constexpr int THREADS      = 512;      // 16 warps -> 32 rows per block

__global__ void __launch_bounds__(THREADS)
shrffn_kernel(const float4* __restrict__ in4,
              float4* __restrict__ out4)
{
    const int lane = threadIdx.x & 31;
    const int r    = lane & 15;                       // position within row-half
    const long long warp_id = (long long)blockIdx.x * (THREADS / 32)
                            + (threadIdx.x >> 5);
    const long long row  = warp_id * 2 + (lane >> 4); // 2 rows per warp
    const long long base = row * 64 + r;              // float4 index

    // 4 independent 128-bit loads (MLP=4), fully coalesced: per i, each
    // warp-half covers a contiguous 256B span; warp covers 2KB total.
    float4 v[4];
#pragma unroll
    for (int i = 0; i < 4; i++) {
        v[i] = in4[base + 16 * i];
    }

    // op_active = element 19 of the row = f4[row*64 + 4].w, held by lane r==4
    // of the same warp-half. Broadcast (all lanes participate).
    float op = __shfl_sync(0xffffffffu, v[0].w, (lane & 16) | 4);

    if (r == 0) {
        // All row inputs are already in registers.
        float a0 = v[0].x;           // in[row*256 + 0]
        float a1 = v[1].x;           // in[row*256 + 64]
        float a2 = v[2].x;           // in[row*256 + 128]
        float a3 = v[3].x;           // in[row*256 + 192]
        float sh_f = v[0].y;         // in[row*256 + 1]

        // Strided-halving tree: (t0+t2) + (t1+t3); power-of-two products exact.
        float t1 = a1 * 256.0f;
        float t2 = a2 * 65536.0f;
        float t3 = a3 * 16777216.0f;
        float val = __fadd_rn(__fadd_rn(a0, t2), __fadd_rn(t1, t3));

        int value_i = (int)val;      // saturating cvt.rzi.s32.f32

        int shift = (int)sh_f;
        if (shift < 0)  shift = 0;
        if (shift > 31) shift = 31;

        int shifted = value_i >> shift;

#pragma unroll
        for (int p = 0; p < 4; p++) {
            v[p].z = (float)((shifted >> (8 * p)) & 255) * op;
        }
    }

#pragma unroll
    for (int i = 0; i < 4; i++) {
        out4[base + 16 * i] = v[i];
    }
}

extern "C" void kernel_launch(void* const* d_in, const int* in_sizes, int n_in,
                              void* d_out, int out_size)
{
    const float* x = (const float*)d_in[0];
    float* out = (float*)d_out;

    // 2 rows per warp, 16 warps per block -> 32 rows per block
    const int blocks = (int)(N_ROWS / 32);            // 8192, exact division

    shrffn_kernel<<<blocks, THREADS>>>((const float4*)x, (float4*)out);
}

// round 16
// speedup vs baseline: 1.0019x; 1.0019x over previous
#include <cuda_runtime.h>
#include <cstdint>

// EfficientSHRFFN — FINAL (R12 configuration; best measured, twice confirmed).
// Bit-exact semantics (locked R4, rel_err == 0.0 on every passing round):
//   B=262144, NPOS=4, D=64; opcode=3, OP_START=16 -> op_active idx 19
//   NIB_A=0, NIB_B=1, RESULT=2
//   value f32 sum order: strided halving (t0+t2)+(t1+t3), products exact
//   astype(int64) under x64-disabled jax -> int32, float->int32 SATURATES
//   shifts/byte-extract in int32
//
// Convergence evidence (wall / ncu, DRAM%):
//   ITEMS=1 T256        : 84.0  / 81.8  75.8%
//   ITEMS=4 T256        : 82.1  / 74.6  81.5%   (.cs hints: 88.8 wall — rejected)
//   ITEMS=8 T256        : 82.4  / 75.9  80.1%   (occ 49% — rejected)
//   ITEMS=4 T512        : 82.0  / 75.4  80.8%
//   reg-map  T256       : 82.7  / 75.2  81.0%
//   persistent 1216 CTA : 92.3  / 79.4  77.5%   (scattered frontier — rejected)
//   reg-map  T512 i64   : 82.0  / 73.9  82.1%  regs 26  <- WINNER (this file)
//     confirmation run  : 82.4  / 74.7  81.3%  (noise band +-0.4us)
//   reg-map  T512 u32   : 81.98 / 74.9  81.2%  regs 32  (tie; worse regs)
//
// Why this is the roofline: issue 9%, alu 6%, fma 2% (SM idle); measured
// DRAM traffic ~= the 512MB logical minimum; 6.45-6.5 TB/s matches the
// path-independent B300 LTS cap (~6300 B/cyc, LDG == TMA). The ~7.5us
// wall-ncu gap is invariant across all 9 variants -> fixed harness cost.

static constexpr long long N_ROWS = 262144;   // B
static constexpr int THREADS      = 512;      // 16 warps -> 32 rows per block

__global__ void __launch_bounds__(THREADS)
shrffn_kernel(const float4* __restrict__ in4,
              float4* __restrict__ out4)
{
    const int lane = threadIdx.x & 31;
    const int r    = lane & 15;                       // position within row-half
    const long long warp_id = (long long)blockIdx.x * (THREADS / 32)
                            + (threadIdx.x >> 5);
    const long long row  = warp_id * 2 + (lane >> 4); // 2 rows per warp
    const long long base = row * 64 + r;              // float4 index

    // 4 independent 128-bit loads (MLP=4), fully coalesced: per i, each
    // warp-half covers a contiguous 256B span; warp covers 2KB total.
    float4 v[4];
#pragma unroll
    for (int i = 0; i < 4; i++) {
        v[i] = in4[base + 16 * i];
    }

    // op_active = element 19 of the row = f4[row*64 + 4].w, held by lane r==4
    // of the same warp-half. Broadcast (all lanes participate).
    float op = __shfl_sync(0xffffffffu, v[0].w, (lane & 16) | 4);

    if (r == 0) {
        // All row inputs are already in registers.
        float a0 = v[0].x;           // in[row*256 + 0]
        float a1 = v[1].x;           // in[row*256 + 64]
        float a2 = v[2].x;           // in[row*256 + 128]
        float a3 = v[3].x;           // in[row*256 + 192]
        float sh_f = v[0].y;         // in[row*256 + 1]

        // Strided-halving tree: (t0+t2) + (t1+t3); power-of-two products exact.
        float t1 = a1 * 256.0f;
        float t2 = a2 * 65536.0f;
        float t3 = a3 * 16777216.0f;
        float val = __fadd_rn(__fadd_rn(a0, t2), __fadd_rn(t1, t3));

        int value_i = (int)val;      // saturating cvt.rzi.s32.f32

        int shift = (int)sh_f;
        if (shift < 0)  shift = 0;
        if (shift > 31) shift = 31;

        int shifted = value_i >> shift;

#pragma unroll
        for (int p = 0; p < 4; p++) {
            v[p].z = (float)((shifted >> (8 * p)) & 255) * op;
        }
    }

#pragma unroll
    for (int i = 0; i < 4; i++) {
        out4[base + 16 * i] = v[i];
    }
}

extern "C" void kernel_launch(void* const* d_in, const int* in_sizes, int n_in,
                              void* d_out, int out_size)
{
    const float* x = (const float*)d_in[0];
    float* out = (float*)d_out;

    // 2 rows per warp, 16 warps per block -> 32 rows per block
    const int blocks = (int)(N_ROWS / 32);            // 8192, exact division

    shrffn_kernel<<<blocks, THREADS>>>((const float4*)x, (float4*)out);
}

// round 17
// speedup vs baseline: 1.0051x; 1.0031x over previous
#include <cuda_runtime.h>
#include <cstdint>

// EfficientSHRFFN — FINAL (R12 configuration; best measured, 3x confirmed).
// Bit-exact semantics (locked R4, rel_err == 0.0 on every passing round):
//   B=262144, NPOS=4, D=64; opcode=3, OP_START=16 -> op_active idx 19
//   NIB_A=0, NIB_B=1, RESULT=2
//   value f32 sum order: strided halving (t0+t2)+(t1+t3), products exact
//   astype(int64) under x64-disabled jax -> int32, float->int32 SATURATES
//   shifts/byte-extract in int32
//
// Convergence evidence (wall / ncu, DRAM%):
//   ITEMS=1 T256        : 84.0  / 81.8  75.8%
//   ITEMS=4 T256        : 82.1  / 74.6  81.5%   (.cs hints: 88.8 wall — rejected;
//                          steady-state replays lose residual-L2 read hits)
//   ITEMS=8 T256        : 82.4  / 75.9  80.1%   (occ 49% — rejected)
//   ITEMS=4 T512        : 82.0  / 75.4  80.8%
//   reg-map  T256       : 82.7  / 75.2  81.0%
//   persistent 1216 CTA : 92.3  / 79.4  77.5%   (scattered frontier — rejected)
//   reg-map  T512 i64   : 82.0 /73.9 | 82.4 /74.7 | 82.2 /74.1   <- WINNER
//   reg-map  T512 u32   : 81.98 / 74.9  (tie; regs 32 vs 26)
//
// Roofline case: issue 9%, alu 6%, fma 2% (SM idle); DRAM traffic ~= the
// 512MB logical minimum; 6.5 TB/s matches the path-independent B300 LTS cap
// (~6300 B/cyc; LDG == TMA, so no mechanism swap helps). Warp stores fully
// cover 128B lines (no write-allocate reads). The ~7.5us wall-ncu gap is
// invariant across all 9 variants -> fixed harness/graph-replay cost.

static constexpr long long N_ROWS = 262144;   // B
static constexpr int THREADS      = 512;      // 16 warps -> 32 rows per block

__global__ void __launch_bounds__(THREADS)
shrffn_kernel(const float4* __restrict__ in4,
              float4* __restrict__ out4)
{
    const int lane = threadIdx.x & 31;
    const int r    = lane & 15;                       // position within row-half
    const long long warp_id = (long long)blockIdx.x * (THREADS / 32)
                            + (threadIdx.x >> 5);
    const long long row  = warp_id * 2 + (lane >> 4); // 2 rows per warp
    const long long base = row * 64 + r;              // float4 index

    // 4 independent 128-bit loads (MLP=4), fully coalesced: per i, each
    // warp-half covers a contiguous 256B span; warp covers 2KB total.
    float4 v[4];
#pragma unroll
    for (int i = 0; i < 4; i++) {
        v[i] = in4[base + 16 * i];
    }

    // op_active = element 19 of the row = f4[row*64 + 4].w, held by lane r==4
    // of the same warp-half. Broadcast (all lanes participate).
    float op = __shfl_sync(0xffffffffu, v[0].w, (lane & 16) | 4);

    if (r == 0) {
        // All row inputs are already in registers.
        float a0 = v[0].x;           // in[row*256 + 0]
        float a1 = v[1].x;           // in[row*256 + 64]
        float a2 = v[2].x;           // in[row*256 + 128]
        float a3 = v[3].x;           // in[row*256 + 192]
        float sh_f = v[0].y;         // in[row*256 + 1]

        // Strided-halving tree: (t0+t2) + (t1+t3); power-of-two products exact.
        float t1 = a1 * 256.0f;
        float t2 = a2 * 65536.0f;
        float t3 = a3 * 16777216.0f;
        float val = __fadd_rn(__fadd_rn(a0, t2), __fadd_rn(t1, t3));

        int value_i = (int)val;      // saturating cvt.rzi.s32.f32

        int shift = (int)sh_f;
        if (shift < 0)  shift = 0;
        if (shift > 31) shift = 31;

        int shifted = value_i >> shift;

#pragma unroll
        for (int p = 0; p < 4; p++) {
            v[p].z = (float)((shifted >> (8 * p)) & 255) * op;
        }
    }

#pragma unroll
    for (int i = 0; i < 4; i++) {
        out4[base + 16 * i] = v[i];
    }
}

extern "C" void kernel_launch(void* const* d_in, const int* in_sizes, int n_in,
                              void* d_out, int out_size)
{
    const float* x = (const float*)d_in[0];
    float* out = (float*)d_out;

    // 2 rows per warp, 16 warps per block -> 32 rows per block
    const int blocks = (int)(N_ROWS / 32);            // 8192, exact division

    shrffn_kernel<<<blocks, THREADS>>>((const float4*)x, (float4*)out);
}